// round 1
// baseline (speedup 1.0000x reference)
#include <cuda_runtime.h>
#include <cuda_bf16.h>

// Problem constants
#define DIMQ 64
#define HIDQ 8
#define BQ   1024
#define NQ   64
#define VQ   8

// Folded-weight device globals (written by precompute kernel)
__device__ float g_s[64];     // strength @ str_w + str_b
__device__ float g_Ak[512];   // [c][j] = sum_d Wk[d][c] * attn_w1[d][j]
__device__ float g_Aq[512];   // [c][j] = sum_d Wq[d][c] * attn_w1[d][j]
__device__ float g_Ap[64];    // [i][j] = sum_d pos_w2[i][d] * attn_w1[d][j]
__device__ float g_cb[8];     // [j]    = sum_d pos_b2[d]*attn_w1[d][j] + attn_b1[j]

__global__ void precompute_kernel(
    const float* __restrict__ strength, const float* __restrict__ str_w,
    const float* __restrict__ str_b,
    const float* __restrict__ q_tbl, const float* __restrict__ k_tbl,
    const float* __restrict__ attn_w1, const float* __restrict__ attn_b1,
    const float* __restrict__ pos_w2, const float* __restrict__ pos_b2,
    const int* __restrict__ embed_id)
{
    const int t = threadIdx.x;
    const int e = embed_id[0];

    if (t < 64) {
        float acc = str_b[t];
        for (int i = 0; i < 512; ++i) acc += strength[i] * str_w[i * 64 + t];
        g_s[t] = acc;
    }
    for (int idx = t; idx < 512; idx += 256) {
        const int c = idx >> 3, j = idx & 7;
        float ak = 0.f, aq = 0.f;
        for (int dd = 0; dd < 64; ++dd) {
            const float w1 = attn_w1[dd * 8 + j];
            ak += k_tbl[e * 4096 + dd * 64 + c] * w1;
            aq += q_tbl[e * 4096 + dd * 64 + c] * w1;
        }
        g_Ak[idx] = ak;
        g_Aq[idx] = aq;
    }
    if (t < 64) {
        const int i = t >> 3, j = t & 7;
        float ap = 0.f;
        for (int dd = 0; dd < 64; ++dd) ap += pos_w2[i * 64 + dd] * attn_w1[dd * 8 + j];
        g_Ap[t] = ap;
    }
    if (t < 8) {
        float cb = attn_b1[t];
        for (int dd = 0; dd < 64; ++dd) cb += pos_b2[dd] * attn_w1[dd * 8 + t];
        g_cb[t] = cb;
    }
}

// Main fused kernel: one block per (b, half of n). 256 threads.
// Chunk = 4 n-rows; thread mapping:
//   phase A : (ln = tid>>6, v = (tid>>3)&7, j = tid&7) -> attn hidden [4][8][8]
//   phase B : (ln = tid>>6, d = tid&63)                -> per-dim softmax + vh + out
__global__ __launch_bounds__(256, 2)
void attn_main(
    const float* __restrict__ q, const float* __restrict__ k,
    const float* __restrict__ pos,
    const float* __restrict__ v_tbl,
    const float* __restrict__ pos_w1, const float* __restrict__ pos_b1,
    const float* __restrict__ pos_w2, const float* __restrict__ pos_b2,
    const float* __restrict__ attn_w2, const float* __restrict__ attn_b2,
    const float* __restrict__ out_w, const float* __restrict__ out_b,
    const int* __restrict__ mask, const int* __restrict__ embed_id,
    float* __restrict__ out)
{
    __shared__ float s_ow[4096];                       // out_w [c][d]
    __shared__ __align__(16) float s_k[32 * 68];       // k rows, stride 68 (pad)
    __shared__ float s_ak[512], s_aq[512];             // folded [c][j]
    __shared__ float s_aw2[512], s_pw2[512];           // [j][d]
    __shared__ float s_q[256], s_x[256];
    __shared__ float s_ph[256], s_hh[256];             // [ln][v][j]
    __shared__ float s_pos[128];                       // [ln][v][4]
    __shared__ float s_ap[64], s_s[64], s_ab2[64], s_pb2[64], s_ob[64];
    __shared__ float s_pw1[32], s_h1q[32];
    __shared__ int   s_mask[32];
    __shared__ float s_cb[8], s_pb1[8];

    const int tid = threadIdx.x;
    const int b = blockIdx.x;
    const int nbase = blockIdx.y * 32;
    const int e = embed_id[0];

    // ---- one-time per-block weight loads ----
    for (int i = tid; i < 4096; i += 256) s_ow[i] = out_w[i];
    for (int i = tid; i < 512; i += 256) {
        s_ak[i]  = g_Ak[i];
        s_aq[i]  = g_Aq[i];
        s_aw2[i] = attn_w2[i];
        s_pw2[i] = pos_w2[i];
    }
    if (tid < 64) {
        s_ap[tid]  = g_Ap[tid];
        s_s[tid]   = g_s[tid];
        s_ab2[tid] = attn_b2[tid];
        s_pb2[tid] = pos_b2[tid];
        s_ob[tid]  = out_b[tid];
    }
    if (tid < 32) s_pw1[tid] = pos_w1[tid];
    if (tid < 8) { s_cb[tid] = g_cb[tid]; s_pb1[tid] = pos_b1[tid]; }

    // Register-cache this thread's Wv row (Wv[d][c], c = 0..63) straight from gmem.
    const int d = tid & 63;
    float wv[64];
    {
        const float* wvg = v_tbl + e * 4096 + d * 64;
        #pragma unroll
        for (int c = 0; c < 64; c += 4) {
            const float4 t4 = *reinterpret_cast<const float4*>(wvg + c);
            wv[c] = t4.x; wv[c + 1] = t4.y; wv[c + 2] = t4.z; wv[c + 3] = t4.w;
        }
    }
    __syncthreads();

    const int j  = tid & 7;
    const int vA = (tid >> 3) & 7;
    const int ln = tid >> 6;

    for (int chunk = 0; chunk < 8; ++chunk) {
        const int n0 = nbase + chunk * 4;
        const long base_n = (long)b * 64 + n0;   // row index into [B*N]

        // ---- cooperative loads for this chunk ----
        s_q[tid] = q[base_n * 64 + tid];
        {
            const float4* kg = reinterpret_cast<const float4*>(k + base_n * 512);
            #pragma unroll
            for (int r = 0; r < 2; ++r) {
                const int i = tid + 256 * r;     // 0..511 float4s
                const int row = i >> 4, c4 = i & 15;
                reinterpret_cast<float4*>(s_k + row * 68)[c4] = kg[i];
            }
        }
        if (tid < 128) s_pos[tid] = pos[base_n * 32 + tid];
        if (tid < 32)  s_mask[tid] = mask[base_n * 8 + tid];
        __syncthreads();

        // ---- phase A1: pos-MLP hidden + q-fold ----
        {
            float acc = s_pb1[j];
            #pragma unroll
            for (int c = 0; c < 4; ++c)
                acc += s_pos[(ln * 8 + vA) * 4 + c] * s_pw1[c * 8 + j];
            s_ph[(ln * 8 + vA) * 8 + j] = fmaxf(acc, 0.f);
            if (vA == 0) {
                float a = 0.f;
                #pragma unroll
                for (int c = 0; c < 64; ++c)
                    a += s_q[ln * 64 + c] * s_aq[c * 8 + j];
                s_h1q[ln * 8 + j] = a;
            }
        }
        __syncthreads();

        // ---- phase A2: attn hidden (folded), relu ----
        {
            float acc = s_cb[j] - s_h1q[ln * 8 + j];
            const float* kr = s_k + (ln * 8 + vA) * 68;
            #pragma unroll
            for (int c = 0; c < 64; ++c) acc += kr[c] * s_ak[c * 8 + j];
            const float* phr = s_ph + (ln * 8 + vA) * 8;
            #pragma unroll
            for (int i2 = 0; i2 < 8; ++i2) acc += phr[i2] * s_ap[i2 * 8 + j];
            s_hh[(ln * 8 + vA) * 8 + j] = fmaxf(acc, 0.f);
        }
        __syncthreads();

        // ---- phase B: per-(ln,d) logits, vh, p, softmax over V ----
        {
            float logit[8], val[8];
            const float ab2 = s_ab2[d], pb2v = s_pb2[d], sd = s_s[d];
            #pragma unroll
            for (int v = 0; v < 8; ++v) {
                const float* hhr = s_hh + (ln * 8 + v) * 8;
                const float* phr = s_ph + (ln * 8 + v) * 8;
                float a2 = ab2, pv = pb2v, vh = sd;
                #pragma unroll
                for (int jj = 0; jj < 8; ++jj) {
                    a2 += hhr[jj] * s_aw2[jj * 64 + d];
                    pv += phr[jj] * s_pw2[jj * 64 + d];
                }
                const float4* kr4 = reinterpret_cast<const float4*>(s_k + (ln * 8 + v) * 68);
                #pragma unroll
                for (int c4 = 0; c4 < 16; ++c4) {
                    const float4 kk = kr4[c4];
                    vh += kk.x * wv[4 * c4] + kk.y * wv[4 * c4 + 1]
                        + kk.z * wv[4 * c4 + 2] + kk.w * wv[4 * c4 + 3];
                }
                logit[v] = (s_mask[ln * 8 + v] == 0) ? -1e9f : a2;
                val[v] = vh + pv;
            }
            float m = logit[0];
            #pragma unroll
            for (int v = 1; v < 8; ++v) m = fmaxf(m, logit[v]);
            float ssum = 0.f, acc = 0.f;
            #pragma unroll
            for (int v = 0; v < 8; ++v) {
                const float ev = __expf(logit[v] - m);
                ssum += ev;
                acc += val[v] * ev;
            }
            s_x[ln * 64 + d] = acc / ssum;
        }
        __syncthreads();

        // ---- output GEMM: y = x @ out_w + out_b ----
        {
            float y = s_ob[d];
            const float* xr = s_x + ln * 64;
            #pragma unroll
            for (int c = 0; c < 64; ++c) y += xr[c] * s_ow[c * 64 + d];
            out[(base_n + ln) * 64 + d] = y;
        }
        // no trailing sync needed: next chunk's post-load barrier orders
        // all smem writes of the next iteration after these reads.
        __syncthreads();
    }
}

extern "C" void kernel_launch(void* const* d_in, const int* in_sizes, int n_in,
                              void* d_out, int out_size)
{
    const float* q        = (const float*)d_in[0];
    const float* k        = (const float*)d_in[1];
    const float* pos      = (const float*)d_in[2];
    const float* strength = (const float*)d_in[3];
    const float* q_tbl    = (const float*)d_in[4];
    const float* k_tbl    = (const float*)d_in[5];
    const float* v_tbl    = (const float*)d_in[6];
    const float* pos_w1   = (const float*)d_in[7];
    const float* pos_b1   = (const float*)d_in[8];
    const float* pos_w2   = (const float*)d_in[9];
    const float* pos_b2   = (const float*)d_in[10];
    const float* attn_w1  = (const float*)d_in[11];
    const float* attn_b1  = (const float*)d_in[12];
    const float* attn_w2  = (const float*)d_in[13];
    const float* attn_b2  = (const float*)d_in[14];
    const float* out_w    = (const float*)d_in[15];
    const float* out_b    = (const float*)d_in[16];
    const float* str_w    = (const float*)d_in[17];
    const float* str_b    = (const float*)d_in[18];
    const int*   mask     = (const int*)d_in[19];
    const int*   embed_id = (const int*)d_in[20];
    float* out = (float*)d_out;

    precompute_kernel<<<1, 256>>>(strength, str_w, str_b, q_tbl, k_tbl,
                                  attn_w1, attn_b1, pos_w2, pos_b2, embed_id);

    dim3 grid(BQ, 2);
    attn_main<<<grid, 256>>>(q, k, pos, v_tbl,
                             pos_w1, pos_b1, pos_w2, pos_b2,
                             attn_w2, attn_b2, out_w, out_b,
                             mask, embed_id, out);
}